// round 1
// baseline (speedup 1.0000x reference)
#include <cuda_runtime.h>
#include <cstdint>

// GATv2Conv for fixed problem shape:
//   N=100000 nodes, E=300000 edges, D_IN=D_OUT=256, neg_slope=0.2
// Pipeline (all on default stream, graph-capturable, no allocations):
//   1) init: zero d_out, zero smax-bits, zero ssum
//   2) tf32 tensor-core GEMM: el = feat@W_src + b_src ; er = feat@W_dst + b_dst
//   3) per-edge score = sum_d lrelu(el[s,d]+er[t,d])*attn[d]; atomicMax per dst
//   4) per-edge ex = exp(score - smax[dst]); atomicAdd ssum[dst]
//   5) per-edge out[dst,:] += (ex/ssum[dst]) * el[src,:]  via red.global.add.v4.f32

#define NMAX 100000
#define EMAX 300000
#define D 256

__device__ __align__(16) float g_el[(size_t)NMAX * D];
__device__ __align__(16) float g_er[(size_t)NMAX * D];
__device__ float    g_score[EMAX];
__device__ float    g_ex[EMAX];
__device__ unsigned g_smaxb[NMAX];
__device__ float    g_ssum[NMAX];

// ---------------------------------------------------------------------------
// helpers
// ---------------------------------------------------------------------------
__device__ __forceinline__ float to_tf32(float x) {
    uint32_t u;
    asm("cvt.rna.tf32.f32 %0, %1;" : "=r"(u) : "f"(x));
    return __uint_as_float(u);
}

__device__ __forceinline__ void mma_tf32(float c[4], const uint32_t a[4], const uint32_t b[2]) {
    asm volatile(
        "mma.sync.aligned.m16n8k8.row.col.f32.tf32.tf32.f32 "
        "{%0,%1,%2,%3}, {%4,%5,%6,%7}, {%8,%9}, {%0,%1,%2,%3};"
        : "+f"(c[0]), "+f"(c[1]), "+f"(c[2]), "+f"(c[3])
        : "r"(a[0]), "r"(a[1]), "r"(a[2]), "r"(a[3]),
          "r"(b[0]), "r"(b[1]));
}

__device__ __forceinline__ void red_add_v4(float* addr, float4 v) {
    asm volatile("red.global.add.v4.f32 [%0], {%1,%2,%3,%4};"
                 :: "l"(addr), "f"(v.x), "f"(v.y), "f"(v.z), "f"(v.w)
                 : "memory");
}

// monotonic float <-> uint encoding for atomicMax over signed floats
__device__ __forceinline__ unsigned enc_f(float x) {
    unsigned b = __float_as_uint(x);
    return (b & 0x80000000u) ? ~b : (b | 0x80000000u);
}
__device__ __forceinline__ float dec_f(unsigned u) {
    unsigned b = (u & 0x80000000u) ? (u ^ 0x80000000u) : ~u;
    return __uint_as_float(b);
}

// ---------------------------------------------------------------------------
// 1) init: zero out (float4), zero smax bits (0 < enc(-inf)=0x007FFFFF), zero ssum
// ---------------------------------------------------------------------------
__global__ void __launch_bounds__(256) init_kernel(float* __restrict__ out, int n4, int N) {
    int i = blockIdx.x * 256 + threadIdx.x;
    if (i < n4) reinterpret_cast<float4*>(out)[i] = make_float4(0.f, 0.f, 0.f, 0.f);
    if (i < N) { g_smaxb[i] = 0u; g_ssum[i] = 0.f; }
}

// ---------------------------------------------------------------------------
// 2) tf32 GEMM: C[M,256] = feat[M,256] @ W[256,256] + bias
//    64x64 tile, BK=32, 4 warps (each warp owns a 64x16 N-slice), m16n8k8 mma
//    blockIdx.z selects (W_src,b_src)->g_el vs (W_dst,b_dst)->g_er
// ---------------------------------------------------------------------------
__global__ void __launch_bounds__(128) gemm_kernel(
    const float* __restrict__ feat,
    const float* __restrict__ Ws, const float* __restrict__ bs,
    const float* __restrict__ Wd, const float* __restrict__ bd,
    int M)
{
    const float* W    = blockIdx.z ? Wd : Ws;
    const float* bias = blockIdx.z ? bd : bs;
    float*       out  = blockIdx.z ? g_er : g_el;

    __shared__ float As[64][36];  // [m][k], pad 4
    __shared__ float Bs[32][68];  // [k][n], pad 4

    const int tid  = threadIdx.x;
    const int warp = tid >> 5, lane = tid & 31;
    const int gid  = lane >> 2, tg = lane & 3;
    const int m0   = blockIdx.x * 64;
    const int n0   = blockIdx.y * 64;

    float acc[4][2][4];
#pragma unroll
    for (int i = 0; i < 4; i++)
#pragma unroll
        for (int j = 0; j < 2; j++)
#pragma unroll
            for (int k = 0; k < 4; k++) acc[i][j][k] = 0.f;

    for (int k0 = 0; k0 < D; k0 += 32) {
        // load A tile (64x32), zero-fill OOB rows
#pragma unroll
        for (int i = 0; i < 4; i++) {
            int f = tid + i * 128;
            int r = f >> 3, c4 = f & 7;
            float4 v = make_float4(0.f, 0.f, 0.f, 0.f);
            int rg = m0 + r;
            if (rg < M) v = *reinterpret_cast<const float4*>(feat + (size_t)rg * D + k0 + c4 * 4);
            As[r][c4 * 4 + 0] = to_tf32(v.x);
            As[r][c4 * 4 + 1] = to_tf32(v.y);
            As[r][c4 * 4 + 2] = to_tf32(v.z);
            As[r][c4 * 4 + 3] = to_tf32(v.w);
        }
        // load B tile (32x64), K=N=256 exact
#pragma unroll
        for (int i = 0; i < 4; i++) {
            int f = tid + i * 128;
            int r = f >> 4, c4 = f & 15;
            float4 v = *reinterpret_cast<const float4*>(W + (size_t)(k0 + r) * D + n0 + c4 * 4);
            Bs[r][c4 * 4 + 0] = to_tf32(v.x);
            Bs[r][c4 * 4 + 1] = to_tf32(v.y);
            Bs[r][c4 * 4 + 2] = to_tf32(v.z);
            Bs[r][c4 * 4 + 3] = to_tf32(v.w);
        }
        __syncthreads();

#pragma unroll
        for (int kk = 0; kk < 4; kk++) {
            const int kb = kk * 8;
            uint32_t a[4][4], b[2][2];
#pragma unroll
            for (int mt = 0; mt < 4; mt++) {
                const int mr = mt * 16;
                a[mt][0] = __float_as_uint(As[mr + gid    ][kb + tg    ]);
                a[mt][1] = __float_as_uint(As[mr + gid + 8][kb + tg    ]);
                a[mt][2] = __float_as_uint(As[mr + gid    ][kb + tg + 4]);
                a[mt][3] = __float_as_uint(As[mr + gid + 8][kb + tg + 4]);
            }
#pragma unroll
            for (int nt = 0; nt < 2; nt++) {
                const int nc = warp * 16 + nt * 8 + gid;
                b[nt][0] = __float_as_uint(Bs[kb + tg    ][nc]);
                b[nt][1] = __float_as_uint(Bs[kb + tg + 4][nc]);
            }
#pragma unroll
            for (int mt = 0; mt < 4; mt++)
#pragma unroll
                for (int nt = 0; nt < 2; nt++)
                    mma_tf32(acc[mt][nt], a[mt], b[nt]);
        }
        __syncthreads();
    }

    // writeback + bias
#pragma unroll
    for (int mt = 0; mt < 4; mt++) {
#pragma unroll
        for (int nt = 0; nt < 2; nt++) {
            const int col = n0 + warp * 16 + nt * 8 + tg * 2;
            const float b0 = bias[col], b1 = bias[col + 1];
            const int r0 = m0 + mt * 16 + gid;
            if (r0 < M) {
                out[(size_t)r0 * D + col    ] = acc[mt][nt][0] + b0;
                out[(size_t)r0 * D + col + 1] = acc[mt][nt][1] + b1;
            }
            const int r1 = r0 + 8;
            if (r1 < M) {
                out[(size_t)r1 * D + col    ] = acc[mt][nt][2] + b0;
                out[(size_t)r1 * D + col + 1] = acc[mt][nt][3] + b1;
            }
        }
    }
}

// ---------------------------------------------------------------------------
// 3) edge score + segment max (1 warp per edge, 8 dims/lane)
// ---------------------------------------------------------------------------
__global__ void __launch_bounds__(256) score_kernel(
    const int* __restrict__ src, const int* __restrict__ dst,
    const float* __restrict__ attn, int E)
{
    __shared__ float s_attn[D];
    const int tid = threadIdx.x;
    s_attn[tid] = attn[tid];
    __syncthreads();

    const int warp = tid >> 5, lane = tid & 31;
    const int e = blockIdx.x * 8 + warp;
    if (e >= E) return;

    const int s = src[e], t = dst[e];
    const float4* pel = reinterpret_cast<const float4*>(g_el + (size_t)s * D) + lane * 2;
    const float4* per = reinterpret_cast<const float4*>(g_er + (size_t)t * D) + lane * 2;
    const float4* pat = reinterpret_cast<const float4*>(s_attn) + lane * 2;

    float sum = 0.f;
#pragma unroll
    for (int j = 0; j < 2; j++) {
        float4 a = pel[j], b = per[j], w = pat[j];
        float x;
        x = a.x + b.x; x = x > 0.f ? x : 0.2f * x; sum += x * w.x;
        x = a.y + b.y; x = x > 0.f ? x : 0.2f * x; sum += x * w.y;
        x = a.z + b.z; x = x > 0.f ? x : 0.2f * x; sum += x * w.z;
        x = a.w + b.w; x = x > 0.f ? x : 0.2f * x; sum += x * w.w;
    }
#pragma unroll
    for (int o = 16; o; o >>= 1) sum += __shfl_xor_sync(0xFFFFFFFFu, sum, o);

    if (lane == 0) {
        g_score[e] = sum;
        atomicMax(&g_smaxb[t], enc_f(sum));
    }
}

// ---------------------------------------------------------------------------
// 4) ex = exp(score - smax[dst]); ssum[dst] += ex
// ---------------------------------------------------------------------------
__global__ void __launch_bounds__(256) ex_kernel(const int* __restrict__ dst, int E)
{
    const int e = blockIdx.x * 256 + threadIdx.x;
    if (e >= E) return;
    const int t = dst[e];
    const float m = dec_f(g_smaxb[t]);
    const float v = expf(g_score[e] - m);
    g_ex[e] = v;
    atomicAdd(&g_ssum[t], v);
}

// ---------------------------------------------------------------------------
// 5) out[dst,:] += (ex/ssum[dst]) * el[src,:]   (1 warp/edge, red.v4)
// ---------------------------------------------------------------------------
__global__ void __launch_bounds__(256) agg_kernel(
    const int* __restrict__ src, const int* __restrict__ dst,
    float* __restrict__ out, int E)
{
    const int tid = threadIdx.x;
    const int warp = tid >> 5, lane = tid & 31;
    const int e = blockIdx.x * 8 + warp;
    if (e >= E) return;

    const int s = src[e], t = dst[e];
    const float a = g_ex[e] / g_ssum[t];

    const float4* pel = reinterpret_cast<const float4*>(g_el + (size_t)s * D) + lane * 2;
    float* po = out + (size_t)t * D + lane * 8;

    float4 v0 = pel[0], v1 = pel[1];
    v0.x *= a; v0.y *= a; v0.z *= a; v0.w *= a;
    v1.x *= a; v1.y *= a; v1.z *= a; v1.w *= a;
    red_add_v4(po, v0);
    red_add_v4(po + 4, v1);
}

// ---------------------------------------------------------------------------
// launch
// ---------------------------------------------------------------------------
extern "C" void kernel_launch(void* const* d_in, const int* in_sizes, int n_in,
                              void* d_out, int out_size)
{
    const float* feat = (const float*)d_in[0];
    const float* Wsrc = (const float*)d_in[1];
    const float* bsrc = (const float*)d_in[2];
    const float* Wdst = (const float*)d_in[3];
    const float* bdst = (const float*)d_in[4];
    const float* attn = (const float*)d_in[5];
    const int*   src  = (const int*)d_in[6];
    const int*   dst  = (const int*)d_in[7];
    float*       out  = (float*)d_out;

    const int N = in_sizes[0] / D;   // 100000
    const int E = in_sizes[6];       // 300000
    const int n4 = out_size / 4;

    // 1) init
    {
        int work = n4 > N ? n4 : N;
        init_kernel<<<(work + 255) / 256, 256>>>(out, n4, N);
    }
    // 2) both GEMMs in one launch (z selects src/dst projection)
    {
        dim3 grid((N + 63) / 64, D / 64, 2);
        gemm_kernel<<<grid, 128>>>(feat, Wsrc, bsrc, Wdst, bdst, N);
    }
    // 3) scores + segment max
    score_kernel<<<(E + 7) / 8, 256>>>(src, dst, attn, E);
    // 4) exp + segment sum
    ex_kernel<<<(E + 255) / 256, 256>>>(dst, E);
    // 5) weighted scatter aggregation
    agg_kernel<<<(E + 7) / 8, 256>>>(src, dst, out, E);
}

// round 5
// speedup vs baseline: 1.4415x; 1.4415x over previous
#include <cuda_runtime.h>
#include <cstdint>

// GATv2Conv, fixed shape: N=100000, E=300000, D_IN=D_OUT=256, neg_slope=0.2
// 1) init kernel: zero d_out, smax-bits, ssum
// 2) tf32 mma.sync GEMM (128x128 tile, cp.async double-buffer): el, er
// 3) edge score + segment-max (atomicMax on monotonic-encoded float)
// 4) ex = exp(score - max); segment-sum
// 5) out[dst] += (ex/ssum)*el[src] via red.global.add.v4.f32

#define NMAX 100000
#define EMAX 300000
#define D 256

__device__ __align__(16) float g_el[(size_t)NMAX * D];
__device__ __align__(16) float g_er[(size_t)NMAX * D];
__device__ float    g_score[EMAX];
__device__ float    g_ex[EMAX];
__device__ unsigned g_smaxb[NMAX];
__device__ float    g_ssum[NMAX];

// ---------------------------------------------------------------------------
__device__ __forceinline__ uint32_t to_tf32_u(float x) {
    uint32_t u;
    asm("cvt.rna.tf32.f32 %0, %1;" : "=r"(u) : "f"(x));
    return u;
}

__device__ __forceinline__ void mma_tf32(float c[4], const uint32_t a[4], const uint32_t b[2]) {
    asm volatile(
        "mma.sync.aligned.m16n8k8.row.col.f32.tf32.tf32.f32 "
        "{%0,%1,%2,%3}, {%4,%5,%6,%7}, {%8,%9}, {%0,%1,%2,%3};"
        : "+f"(c[0]), "+f"(c[1]), "+f"(c[2]), "+f"(c[3])
        : "r"(a[0]), "r"(a[1]), "r"(a[2]), "r"(a[3]),
          "r"(b[0]), "r"(b[1]));
}

__device__ __forceinline__ void cp_async16(uint32_t smem_addr, const void* gptr, int src_bytes) {
    asm volatile("cp.async.ca.shared.global [%0], [%1], 16, %2;"
                 :: "r"(smem_addr), "l"(gptr), "r"(src_bytes));
}
__device__ __forceinline__ void cp_commit() {
    asm volatile("cp.async.commit_group;");
}
template <int N_>
__device__ __forceinline__ void cp_wait() {
    asm volatile("cp.async.wait_group %0;" :: "n"(N_));
}

__device__ __forceinline__ void red_add_v4(float* addr, float4 v) {
    asm volatile("red.global.add.v4.f32 [%0], {%1,%2,%3,%4};"
                 :: "l"(addr), "f"(v.x), "f"(v.y), "f"(v.z), "f"(v.w)
                 : "memory");
}

// monotonic float <-> uint encoding for atomicMax over signed floats
__device__ __forceinline__ unsigned enc_f(float x) {
    unsigned b = __float_as_uint(x);
    return (b & 0x80000000u) ? ~b : (b | 0x80000000u);
}
__device__ __forceinline__ float dec_f(unsigned u) {
    unsigned b = (u & 0x80000000u) ? (u ^ 0x80000000u) : ~u;
    return __uint_as_float(b);
}

// ---------------------------------------------------------------------------
// 1) init: zero out (float4), zero smax bits, zero ssum  (known-good pattern)
// ---------------------------------------------------------------------------
__global__ void __launch_bounds__(256) init_kernel(float* __restrict__ out, int n4, int N) {
    int i = blockIdx.x * 256 + threadIdx.x;
    if (i < n4) reinterpret_cast<float4*>(out)[i] = make_float4(0.f, 0.f, 0.f, 0.f);
    if (i < N) { g_smaxb[i] = 0u; g_ssum[i] = 0.f; }
}

// ---------------------------------------------------------------------------
// 2) tf32 GEMM: C[M,256] = feat[M,256] @ W[256,256] + bias
//    BM=128, BN=128, BK=16, 256 thr (8 warps, 2x4), warp tile 64x32.
//    cp.async double-buffered. blockIdx.z: 0 -> g_el (W_src), 1 -> g_er (W_dst)
// ---------------------------------------------------------------------------
#define BK 16
#define K_ITERS (D / BK)   // 16

__global__ void __launch_bounds__(256) gemm_kernel(
    const float* __restrict__ feat,
    const float* __restrict__ Ws, const float* __restrict__ bs,
    const float* __restrict__ Wd, const float* __restrict__ bd,
    int M)
{
    const float* W    = blockIdx.z ? Wd : Ws;
    const float* bias = blockIdx.z ? bd : bs;
    float*       out  = blockIdx.z ? g_er : g_el;

    __shared__ float As[2][128][20];   // [stage][m][k] pad->20
    __shared__ float Bs[2][BK][136];   // [stage][k][n] pad->136

    const int tid    = threadIdx.x;
    const int warp   = tid >> 5, lane = tid & 31;
    const int warp_m = warp & 1;        // 0..1
    const int warp_n = warp >> 1;       // 0..3
    const int gid    = lane >> 2, tg = lane & 3;
    const int m0     = blockIdx.x * 128;
    const int n0     = blockIdx.y * 128;

    // per-thread load coords
    const int ar  = tid >> 2;           // A row 0..63 (+64 on 2nd)
    const int ac4 = tid & 3;            // A float4-col 0..3
    const int br  = tid >> 5;           // B row 0..7 (+8 on 2nd)
    const int bc4 = tid & 31;           // B float4-col 0..31

    float acc[4][4][4];
#pragma unroll
    for (int i = 0; i < 4; i++)
#pragma unroll
        for (int j = 0; j < 4; j++)
#pragma unroll
            for (int k = 0; k < 4; k++) acc[i][j][k] = 0.f;

    auto load_stage = [&](int stage, int k0) {
#pragma unroll
        for (int i = 0; i < 2; i++) {
            int r  = ar + i * 64;
            int rg = m0 + r;
            uint32_t daddr = (uint32_t)__cvta_generic_to_shared(&As[stage][r][ac4 * 4]);
            const void* src = feat + (size_t)rg * D + k0 + ac4 * 4;
            cp_async16(daddr, src, rg < M ? 16 : 0);
        }
#pragma unroll
        for (int i = 0; i < 2; i++) {
            int r = br + i * 8;
            uint32_t daddr = (uint32_t)__cvta_generic_to_shared(&Bs[stage][r][bc4 * 4]);
            const void* src = W + (size_t)(k0 + r) * D + n0 + bc4 * 4;
            cp_async16(daddr, src, 16);
        }
        cp_commit();
    };

    load_stage(0, 0);

    for (int it = 0; it < K_ITERS; it++) {
        const int stage = it & 1;
        if (it + 1 < K_ITERS) {
            load_stage(stage ^ 1, (it + 1) * BK);
            cp_wait<1>();
        } else {
            cp_wait<0>();
        }
        __syncthreads();

#pragma unroll
        for (int kk = 0; kk < 2; kk++) {
            const int kb = kk * 8;
            uint32_t a[4][4], b[4][2];
#pragma unroll
            for (int mt = 0; mt < 4; mt++) {
                const int mr = warp_m * 64 + mt * 16;
                a[mt][0] = to_tf32_u(As[stage][mr + gid    ][kb + tg    ]);
                a[mt][1] = to_tf32_u(As[stage][mr + gid + 8][kb + tg    ]);
                a[mt][2] = to_tf32_u(As[stage][mr + gid    ][kb + tg + 4]);
                a[mt][3] = to_tf32_u(As[stage][mr + gid + 8][kb + tg + 4]);
            }
#pragma unroll
            for (int nt = 0; nt < 4; nt++) {
                const int nc = warp_n * 32 + nt * 8 + gid;
                b[nt][0] = to_tf32_u(Bs[stage][kb + tg    ][nc]);
                b[nt][1] = to_tf32_u(Bs[stage][kb + tg + 4][nc]);
            }
#pragma unroll
            for (int mt = 0; mt < 4; mt++)
#pragma unroll
                for (int nt = 0; nt < 4; nt++)
                    mma_tf32(acc[mt][nt], a[mt], b[nt]);
        }
        __syncthreads();
    }

    // writeback + bias (float2 stores)
#pragma unroll
    for (int mt = 0; mt < 4; mt++) {
#pragma unroll
        for (int nt = 0; nt < 4; nt++) {
            const int col = n0 + warp_n * 32 + nt * 8 + tg * 2;
            const float b0 = bias[col], b1 = bias[col + 1];
            const int r0 = m0 + warp_m * 64 + mt * 16 + gid;
            if (r0 < M) {
                float2 v = make_float2(acc[mt][nt][0] + b0, acc[mt][nt][1] + b1);
                *reinterpret_cast<float2*>(out + (size_t)r0 * D + col) = v;
            }
            const int r1 = r0 + 8;
            if (r1 < M) {
                float2 v = make_float2(acc[mt][nt][2] + b0, acc[mt][nt][3] + b1);
                *reinterpret_cast<float2*>(out + (size_t)r1 * D + col) = v;
            }
        }
    }
}

// ---------------------------------------------------------------------------
// 3) edge score + segment max (1 warp per edge)
// ---------------------------------------------------------------------------
__global__ void __launch_bounds__(256) score_kernel(
    const int* __restrict__ src, const int* __restrict__ dst,
    const float* __restrict__ attn, int E)
{
    __shared__ float s_attn[D];
    const int tid = threadIdx.x;
    s_attn[tid] = attn[tid];
    __syncthreads();

    const int warp = tid >> 5, lane = tid & 31;
    const int e = blockIdx.x * 8 + warp;
    if (e >= E) return;

    const int s = src[e], t = dst[e];
    const float4* pel = reinterpret_cast<const float4*>(g_el + (size_t)s * D) + lane * 2;
    const float4* per = reinterpret_cast<const float4*>(g_er + (size_t)t * D) + lane * 2;
    const float4* pat = reinterpret_cast<const float4*>(s_attn) + lane * 2;

    float sum = 0.f;
#pragma unroll
    for (int j = 0; j < 2; j++) {
        float4 a = pel[j], b = per[j], w = pat[j];
        float x;
        x = a.x + b.x; x = x > 0.f ? x : 0.2f * x; sum += x * w.x;
        x = a.y + b.y; x = x > 0.f ? x : 0.2f * x; sum += x * w.y;
        x = a.z + b.z; x = x > 0.f ? x : 0.2f * x; sum += x * w.z;
        x = a.w + b.w; x = x > 0.f ? x : 0.2f * x; sum += x * w.w;
    }
#pragma unroll
    for (int o = 16; o; o >>= 1) sum += __shfl_xor_sync(0xFFFFFFFFu, sum, o);

    if (lane == 0) {
        g_score[e] = sum;
        atomicMax(&g_smaxb[t], enc_f(sum));
    }
}

// ---------------------------------------------------------------------------
// 4) ex = exp(score - smax[dst]); ssum[dst] += ex
// ---------------------------------------------------------------------------
__global__ void __launch_bounds__(256) ex_kernel(const int* __restrict__ dst, int E)
{
    const int e = blockIdx.x * 256 + threadIdx.x;
    if (e >= E) return;
    const int t = dst[e];
    const float m = dec_f(g_smaxb[t]);
    const float v = expf(g_score[e] - m);
    g_ex[e] = v;
    atomicAdd(&g_ssum[t], v);
}

// ---------------------------------------------------------------------------
// 5) out[dst,:] += (ex/ssum[dst]) * el[src,:]   (1 warp/edge, red.v4)
// ---------------------------------------------------------------------------
__global__ void __launch_bounds__(256) agg_kernel(
    const int* __restrict__ src, const int* __restrict__ dst,
    float* __restrict__ out, int E)
{
    const int tid = threadIdx.x;
    const int warp = tid >> 5, lane = tid & 31;
    const int e = blockIdx.x * 8 + warp;
    if (e >= E) return;

    const int s = src[e], t = dst[e];
    const float a = g_ex[e] / g_ssum[t];

    const float4* pel = reinterpret_cast<const float4*>(g_el + (size_t)s * D) + lane * 2;
    float* po = out + (size_t)t * D + lane * 8;

    float4 v0 = pel[0], v1 = pel[1];
    v0.x *= a; v0.y *= a; v0.z *= a; v0.w *= a;
    v1.x *= a; v1.y *= a; v1.z *= a; v1.w *= a;
    red_add_v4(po, v0);
    red_add_v4(po + 4, v1);
}

// ---------------------------------------------------------------------------
// launch
// ---------------------------------------------------------------------------
extern "C" void kernel_launch(void* const* d_in, const int* in_sizes, int n_in,
                              void* d_out, int out_size)
{
    const float* feat = (const float*)d_in[0];
    const float* Wsrc = (const float*)d_in[1];
    const float* bsrc = (const float*)d_in[2];
    const float* Wdst = (const float*)d_in[3];
    const float* bdst = (const float*)d_in[4];
    const float* attn = (const float*)d_in[5];
    const int*   src  = (const int*)d_in[6];
    const int*   dst  = (const int*)d_in[7];
    float*       out  = (float*)d_out;

    const int N = in_sizes[0] / D;   // 100000
    const int E = in_sizes[6];       // 300000
    const int n4 = out_size / 4;

    // 1) init (single kernel, known-good capturable pattern)
    {
        int work = n4 > N ? n4 : N;
        init_kernel<<<(work + 255) / 256, 256>>>(out, n4, N);
    }
    // 2) both GEMMs in one launch (z selects src/dst projection)
    {
        dim3 grid((N + 127) / 128, D / 128, 2);
        gemm_kernel<<<grid, 256>>>(feat, Wsrc, bsrc, Wdst, bdst, N);
    }
    // 3) scores + segment max
    score_kernel<<<(E + 7) / 8, 256>>>(src, dst, attn, E);
    // 4) exp + segment sum
    ex_kernel<<<(E + 255) / 256, 256>>>(dst, E);
    // 5) weighted scatter aggregation
    agg_kernel<<<(E + 7) / 8, 256>>>(src, dst, out, E);
}